// round 13
// baseline (speedup 1.0000x reference)
#include <cuda_runtime.h>
#include <cstdint>
#include <cstddef>

#define SEQ   4096
#define BATCH 8
#define DM    512
#define NHEAD 8
#define DK    64
#define PHI   128
#define ROWS  (SEQ * BATCH)    // 32768 tokens
#define NG    1664             // fused QKV+gate GEMM width
#define PAD   4

typedef unsigned long long ull;

// ---------------------------------------------------------------------------
// Static device scratch
// ---------------------------------------------------------------------------
__device__ float g_xr  [(size_t)ROWS * DM];
__device__ float g_wcat[(size_t)DM * NG];
__device__ float g_wo  [(size_t)DM * DM];
__device__ float g_qkv [(size_t)(ROWS + PAD * BATCH) * NG];
__device__ float g_qphi[(size_t)(ROWS + PAD * BATCH) * NHEAD * PHI];
__device__ float g_kphi[(size_t)(ROWS + PAD * BATCH) * NHEAD * PHI];
__device__ float g_bc  [(size_t)(ROWS + PAD * BATCH) * NHEAD * 2];
__device__ float g_att [(size_t)ROWS * DM];

// ---------------------------------------------------------------------------
// helpers
// ---------------------------------------------------------------------------
__device__ __forceinline__ uint32_t f2tf32(float x) {
    uint32_t r;
    asm("cvt.rna.tf32.f32 %0, %1;" : "=r"(r) : "f"(x));
    return r;
}
__device__ __forceinline__ float rnd_tf32(float x) {
    return __uint_as_float(f2tf32(x));
}
__device__ __forceinline__ void mma_tf32(float c[4], const uint32_t a[4], const uint32_t b[2]) {
    asm volatile(
        "mma.sync.aligned.m16n8k8.row.col.f32.tf32.tf32.f32 "
        "{%0,%1,%2,%3}, {%4,%5,%6,%7}, {%8,%9}, {%0,%1,%2,%3};\n"
        : "+f"(c[0]), "+f"(c[1]), "+f"(c[2]), "+f"(c[3])
        : "r"(a[0]), "r"(a[1]), "r"(a[2]), "r"(a[3]), "r"(b[0]), "r"(b[1]));
}
__device__ __forceinline__ void cp_async16(uint32_t s, const void* g) {
    asm volatile("cp.async.cg.shared.global [%0], [%1], 16;\n" :: "r"(s), "l"(g));
}
__device__ __forceinline__ void cp_commit() {
    asm volatile("cp.async.commit_group;\n" ::: "memory");
}
__device__ __forceinline__ void cp_wait0() {
    asm volatile("cp.async.wait_group 0;\n" ::: "memory");
}
__device__ __forceinline__ uint32_t ldu(const float* p) {
    return *reinterpret_cast<const uint32_t*>(p);
}

// ---------------------------------------------------------------------------
// Elementwise pre-round passes
// ---------------------------------------------------------------------------
__global__ void __launch_bounds__(256)
round_f4(const float* __restrict__ in, float* __restrict__ out) {
    size_t i = ((size_t)blockIdx.x * 256 + threadIdx.x) * 4;
    float4 v = *reinterpret_cast<const float4*>(in + i);
    v.x = rnd_tf32(v.x); v.y = rnd_tf32(v.y); v.z = rnd_tf32(v.z); v.w = rnd_tf32(v.w);
    *reinterpret_cast<float4*>(out + i) = v;
}

__global__ void __launch_bounds__(256)
concat_w(const float* __restrict__ Wq, const float* __restrict__ Wk,
         const float* __restrict__ Wv, const float* __restrict__ Wg,
         float* __restrict__ wc) {
    int idx = blockIdx.x * 256 + threadIdx.x;
    int r = idx / NG, c = idx - r * NG;
    float v = 0.f;
    if      (c < 512)  v = Wq[r * 512 + c];
    else if (c < 1024) v = Wk[r * 512 + c - 512];
    else if (c < 1536) v = Wv[r * 512 + c - 1024];
    else if (c < 1544) v = Wg[r * 8 + c - 1536];
    wc[idx] = rnd_tf32(v);
}

// ---------------------------------------------------------------------------
// GEMM: C = A*B (+bias), tf32 tensor cores, 128x128x32, cp.async pipelined.
// ---------------------------------------------------------------------------
#define BM 128
#define BN 128
#define BK 32
#define AST 36
#define BST 136
#define STAGE_F (BM * AST + BK * BST)
#define GEMM_SMEM_BYTES (2 * STAGE_F * 4)

__global__ void __launch_bounds__(256, 2)
gemm_tf32(const float* __restrict__ A, const float* __restrict__ B,
          const float* __restrict__ bias, float* __restrict__ C,
          int M, int N, int K)
{
    extern __shared__ float smemf[];

    const int tid  = threadIdx.x;
    const int warp = tid >> 5;
    const int lane = tid & 31;
    const int wm   = warp >> 2;
    const int wn   = warp & 3;
    const int g    = lane >> 2;
    const int t4   = lane & 3;
    const int rowBase = blockIdx.y * BM;
    const int colBase = blockIdx.x * BN;

    const int ar = tid >> 3, ac = (tid & 7) << 2;
    const int br = tid >> 5, bc = (tid & 31) << 2;

    float acc[4][4][4];
    #pragma unroll
    for (int i = 0; i < 4; ++i)
        #pragma unroll
        for (int j = 0; j < 4; ++j)
            #pragma unroll
            for (int r = 0; r < 4; ++r) acc[i][j][r] = 0.f;

    auto load_tile = [&](int stage, int k0) {
        float* as = smemf + stage * STAGE_F;
        float* bs = as + BM * AST;
        const float* ag = A + (size_t)(rowBase + ar) * K + k0 + ac;
        uint32_t asa = (uint32_t)__cvta_generic_to_shared(as + ar * AST + ac);
        #pragma unroll
        for (int i = 0; i < 4; ++i)
            cp_async16(asa + i * 32 * AST * 4, ag + (size_t)i * 32 * K);
        const float* bg = B + (size_t)(k0 + br) * N + colBase + bc;
        uint32_t bsa = (uint32_t)__cvta_generic_to_shared(bs + br * BST + bc);
        #pragma unroll
        for (int i = 0; i < 4; ++i)
            cp_async16(bsa + i * 8 * BST * 4, bg + (size_t)i * 8 * N);
        cp_commit();
    };

    const int NK = K / BK;
    load_tile(0, 0);

    for (int it = 0; it < NK; ++it) {
        cp_wait0();
        __syncthreads();
        if (it + 1 < NK) load_tile((it + 1) & 1, (it + 1) * BK);

        const uint32_t* as = reinterpret_cast<const uint32_t*>(smemf + (it & 1) * STAGE_F);
        const uint32_t* bs = as + BM * AST;

        #pragma unroll
        for (int kk = 0; kk < BK; kk += 8) {
            uint32_t afr[4][4];
            uint32_t bfr[4][2];
            #pragma unroll
            for (int mt = 0; mt < 4; ++mt) {
                int r0 = wm * 64 + mt * 16;
                afr[mt][0] = as[(r0 + g)     * AST + kk + t4];
                afr[mt][1] = as[(r0 + 8 + g) * AST + kk + t4];
                afr[mt][2] = as[(r0 + g)     * AST + kk + 4 + t4];
                afr[mt][3] = as[(r0 + 8 + g) * AST + kk + 4 + t4];
            }
            #pragma unroll
            for (int nt = 0; nt < 4; ++nt) {
                int c0 = wn * 32 + nt * 8;
                bfr[nt][0] = bs[(kk + t4)     * BST + c0 + g];
                bfr[nt][1] = bs[(kk + 4 + t4) * BST + c0 + g];
            }
            #pragma unroll
            for (int mt = 0; mt < 4; ++mt)
                #pragma unroll
                for (int nt = 0; nt < 4; ++nt)
                    mma_tf32(acc[mt][nt], afr[mt], bfr[nt]);
        }
    }

    #pragma unroll
    for (int mt = 0; mt < 4; ++mt) {
        int r = rowBase + wm * 64 + mt * 16 + g;
        #pragma unroll
        for (int nt = 0; nt < 4; ++nt) {
            int c = colBase + wn * 32 + nt * 8 + 2 * t4;
            float b0 = 0.f, b1 = 0.f;
            if (bias) { b0 = bias[c]; b1 = bias[c + 1]; }
            C[(size_t)r * N + c]           = acc[mt][nt][0] + b0;
            C[(size_t)r * N + c + 1]       = acc[mt][nt][1] + b1;
            C[(size_t)(r + 8) * N + c]     = acc[mt][nt][2] + b0;
            C[(size_t)(r + 8) * N + c + 1] = acc[mt][nt][3] + b1;
        }
    }
}

// ---------------------------------------------------------------------------
// bc[t,h].x = sigmoid(qkv[t,1536+h])
// ---------------------------------------------------------------------------
__global__ void __launch_bounds__(256)
extract_beta(const float* __restrict__ qkv, float* __restrict__ bcv) {
    int idx = blockIdx.x * 256 + threadIdx.x;
    int t = idx >> 3, h = idx & 7;
    float a = qkv[(size_t)t * NG + 1536 + h];
    bcv[idx * 2] = 1.f / (1.f + expf(-a));
}

// ---------------------------------------------------------------------------
// DPFP. One warp per (token, head).
// ---------------------------------------------------------------------------
__global__ void __launch_bounds__(256)
dpfp_kernel(const float* __restrict__ raw, float* __restrict__ phi)
{
    const int t    = blockIdx.x;
    const int h    = threadIdx.x >> 5;
    const int lane = threadIdx.x & 31;

    const float4 xv = *reinterpret_cast<const float4*>(
        raw + (size_t)t * NG + h * DK + ((lane & 15) << 2));
    const float sgn = (lane < 16) ? 1.f : -1.f;
    float a0 = fmaxf(sgn * xv.x, 0.f);
    float a1 = fmaxf(sgn * xv.y, 0.f);
    float a2 = fmaxf(sgn * xv.z, 0.f);
    float a3 = fmaxf(sgn * xv.w, 0.f);

    float nbr = __shfl_sync(0xffffffffu, a3, (lane + 31) & 31);
    float y0 = a0 * nbr;
    float y1 = a1 * a0;
    float y2 = a2 * a1;
    float y3 = a3 * a2;

    float s = (y0 + y1) + (y2 + y3);
    #pragma unroll
    for (int off = 16; off > 0; off >>= 1)
        s += __shfl_xor_sync(0xffffffffu, s, off);
    float r = 1.f / (s + 1e-6f);

    float4 o = make_float4(y0 * r, y1 * r, y2 * r, y3 * r);
    *reinterpret_cast<float4*>(phi + ((size_t)t * NHEAD + h) * PHI + (lane << 2)) = o;
}

// ---------------------------------------------------------------------------
// Chunked delta rule. 128 CTAs: (pair = b*8+h, v-half). 64 chunks of 64
// tokens. Per chunk (tf32 MMA, W carried as hi+lo tf32 pair ~ fp32):
//   A = K Kt; G = tril(Q Kt); rhs = V - K Wt; forward-substitute D;
//   OUT = trilG D + Q Wt; W += Dt K.
// ---------------------------------------------------------------------------
#define NCH   64
#define CT    64
#define VHW   32
#define LKQ   132
#define LA    68
#define LD    36
#define OKQ_ST (CT * LKQ)                 // 8448 floats per K/Q stage
#define OFF_K   0
#define OFF_Q   (2 * OKQ_ST)              // 16896
#define OFF_WHI (4 * OKQ_ST)              // 33792
#define OFF_WLO (OFF_WHI + VHW * LKQ)     // 38016
#define OFF_A   (OFF_WLO + VHW * LKQ)     // 42240
#define OFF_G   (OFF_A + CT * LA)         // 46592
#define OFF_V   (OFF_G + CT * LA)         // 50944
#define OFF_D   (OFF_V + CT * LD)         // 53248
#define OFF_B   (OFF_D + CT * LD)         // 55552
#define CH_SMEM_F (OFF_B + 64)            // 55616
#define CH_SMEM_BYTES (CH_SMEM_F * 4)     // 222464

// one warp-level tiled GEMM pass accumulating into acc[NT][4]
__device__ __forceinline__ void gemm_block(
    const float* As, int lda, bool cvtA, bool trA,
    const float* Bsm, int ldb, bool cvtB, bool trB,
    float acc[][4], int NT, int m0, int n0, int K, int g, int t4)
{
    for (int kk = 0; kk < K; kk += 8) {
        uint32_t a[4];
        if (!trA) {
            const float* p0 = As + (m0 + g) * lda + kk + t4;
            const float* p1 = As + (m0 + 8 + g) * lda + kk + t4;
            a[0] = ldu(p0); a[1] = ldu(p1); a[2] = ldu(p0 + 4); a[3] = ldu(p1 + 4);
        } else {
            const float* p0 = As + (kk + t4) * lda + m0 + g;
            const float* p1 = As + (kk + 4 + t4) * lda + m0 + g;
            a[0] = ldu(p0); a[1] = ldu(p0 + 8); a[2] = ldu(p1); a[3] = ldu(p1 + 8);
        }
        if (cvtA) {
            #pragma unroll
            for (int i = 0; i < 4; ++i) a[i] = f2tf32(__uint_as_float(a[i]));
        }
        for (int nt = 0; nt < NT; ++nt) {
            uint32_t bfr[2];
            int nb = n0 + nt * 8 + g;
            if (!trB) {
                bfr[0] = ldu(Bsm + nb * ldb + kk + t4);
                bfr[1] = ldu(Bsm + nb * ldb + kk + 4 + t4);
            } else {
                bfr[0] = ldu(Bsm + (kk + t4) * ldb + nb);
                bfr[1] = ldu(Bsm + (kk + 4 + t4) * ldb + nb);
            }
            if (cvtB) {
                bfr[0] = f2tf32(__uint_as_float(bfr[0]));
                bfr[1] = f2tf32(__uint_as_float(bfr[1]));
            }
            mma_tf32(acc[nt], a, bfr);
        }
    }
}

__global__ void __launch_bounds__(256, 1)
chunk_kernel(const float* __restrict__ qphi, const float* __restrict__ kphi,
             const float* __restrict__ qkv, const float* __restrict__ bcv,
             float* __restrict__ att)
{
    extern __shared__ float sm[];
    const int tid  = threadIdx.x;
    const int w    = tid >> 5;
    const int lane = tid & 31;
    const int g    = lane >> 2;
    const int t4   = lane & 3;
    const int pair = blockIdx.x >> 1;
    const int vh   = blockIdx.x & 1;
    const int b    = pair >> 3;
    const int h    = pair & 7;

    float* Ks  = sm + OFF_K;
    float* Qs  = sm + OFF_Q;
    float* Whi = sm + OFF_WHI;
    float* Wlo = sm + OFF_WLO;
    float* Asm = sm + OFF_A;
    float* Gsm = sm + OFF_G;
    float* Vs  = sm + OFF_V;
    float* Ds  = sm + OFF_D;
    float* Bts = sm + OFF_B;

    // zero W
    for (int idx = tid; idx < VHW * LKQ; idx += 256) { Whi[idx] = 0.f; Wlo[idx] = 0.f; }

    const int wr = w & 3, wc = w >> 2;

    // issue cp.async for chunk c's K and Q into stage c&1
    auto issueKQ = [&](int c) {
        int st = (c & 1) * OKQ_ST;
        for (int idx = tid; idx < 2048; idx += 256) {
            int i = idx >> 5, sg = idx & 31;
            size_t s_time = (size_t)c * CT + i;
            const float* ksrc = kphi + s_time * 8192 + pair * PHI + sg * 4;
            const float* qsrc = qphi + s_time * 8192 + pair * PHI + sg * 4;
            cp_async16((uint32_t)__cvta_generic_to_shared(Ks + st + i * LKQ + sg * 4), ksrc);
            cp_async16((uint32_t)__cvta_generic_to_shared(Qs + st + i * LKQ + sg * 4), qsrc);
        }
        cp_commit();
    };

    issueKQ(0);

    for (int c = 0; c < NCH; ++c) {
        const int st = (c & 1) * OKQ_ST;
        const float* Kc = Ks + st;
        const float* Qc = Qs + st;

        // V + beta loads for this chunk
        for (int idx = tid; idx < 512; idx += 256) {
            int i = idx >> 3, sg = idx & 7;
            const float4 v4 = *reinterpret_cast<const float4*>(
                qkv + (size_t)((c * CT + i) * BATCH + b) * NG + 1024 + h * DK + vh * VHW + sg * 4);
            Vs[i * LD + sg * 4 + 0] = v4.x;
            Vs[i * LD + sg * 4 + 1] = v4.y;
            Vs[i * LD + sg * 4 + 2] = v4.z;
            Vs[i * LD + sg * 4 + 3] = v4.w;
        }
        if (tid < 64)
            Bts[tid] = bcv[((size_t)(c * CT + tid) * 64 + pair) * 2];

        cp_wait0();
        __syncthreads();

        // convert K/Q stage to tf32 in place
        for (int idx = tid; idx < 8192; idx += 256) {
            int i = idx >> 7, col = idx & 127;
            float* kp = const_cast<float*>(Kc) + i * LKQ + col;
            float* qp = const_cast<float*>(Qc) + i * LKQ + col;
            *kp = rnd_tf32(*kp);
            *qp = rnd_tf32(*qp);
        }
        __syncthreads();

        if (c + 1 < NCH) issueKQ(c + 1);

        // (1) A = K Kt  [64x64], k=128   (store fp32)
        {
            float acc[4][4];
            #pragma unroll
            for (int i = 0; i < 4; ++i)
                #pragma unroll
                for (int r = 0; r < 4; ++r) acc[i][r] = 0.f;
            gemm_block(Kc, LKQ, false, false, Kc, LKQ, false, false,
                       acc, 4, 16 * wr, 32 * wc, 128, g, t4);
            #pragma unroll
            for (int nt = 0; nt < 4; ++nt) {
                int r0 = 16 * wr + g, cc = 32 * wc + nt * 8 + 2 * t4;
                Asm[r0 * LA + cc]           = acc[nt][0];
                Asm[r0 * LA + cc + 1]       = acc[nt][1];
                Asm[(r0 + 8) * LA + cc]     = acc[nt][2];
                Asm[(r0 + 8) * LA + cc + 1] = acc[nt][3];
            }
        }
        // (2) G = tril(Q Kt) incl diag  (store fp32, masked)
        {
            float acc[4][4];
            #pragma unroll
            for (int i = 0; i < 4; ++i)
                #pragma unroll
                for (int r = 0; r < 4; ++r) acc[i][r] = 0.f;
            gemm_block(Qc, LKQ, false, false, Kc, LKQ, false, false,
                       acc, 4, 16 * wr, 32 * wc, 128, g, t4);
            #pragma unroll
            for (int nt = 0; nt < 4; ++nt) {
                int r0 = 16 * wr + g, cc = 32 * wc + nt * 8 + 2 * t4;
                Gsm[r0 * LA + cc]           = (cc     <= r0)     ? acc[nt][0] : 0.f;
                Gsm[r0 * LA + cc + 1]       = (cc + 1 <= r0)     ? acc[nt][1] : 0.f;
                Gsm[(r0 + 8) * LA + cc]     = (cc     <= r0 + 8) ? acc[nt][2] : 0.f;
                Gsm[(r0 + 8) * LA + cc + 1] = (cc + 1 <= r0 + 8) ? acc[nt][3] : 0.f;
            }
        }
        // (3) rhs = V - K Wt  [64x32], k=128 twice (hi, lo)
        {
            float acc[2][4];
            #pragma unroll
            for (int i = 0; i < 2; ++i)
                #pragma unroll
                for (int r = 0; r < 4; ++r) acc[i][r] = 0.f;
            gemm_block(Kc, LKQ, false, false, Whi, LKQ, false, false,
                       acc, 2, 16 * wr, 16 * wc, 128, g, t4);
            gemm_block(Kc, LKQ, false, false, Wlo, LKQ, false, false,
                       acc, 2, 16 * wr, 16 * wc, 128, g, t4);
            #pragma unroll
            for (int nt = 0; nt < 2; ++nt) {
                int r0 = 16 * wr + g, cc = 16 * wc + nt * 8 + 2 * t4;
                Ds[r0 * LD + cc]           = Vs[r0 * LD + cc]           - acc[nt][0];
                Ds[r0 * LD + cc + 1]       = Vs[r0 * LD + cc + 1]       - acc[nt][1];
                Ds[(r0 + 8) * LD + cc]     = Vs[(r0 + 8) * LD + cc]     - acc[nt][2];
                Ds[(r0 + 8) * LD + cc + 1] = Vs[(r0 + 8) * LD + cc + 1] - acc[nt][3];
            }
        }
        __syncthreads();

        // forward substitution: d_i = beta_i (rhs_i - sum_{j<i} A[i,j] d_j)
        // blocked by 8 tokens: serial in-block solve (32 threads), rank-8 update
        for (int blk = 0; blk < 8; ++blk) {
            int j0 = blk * 8;
            if (tid < VHW) {
                int v = tid;
                float dv[8];
                #pragma unroll
                for (int l = 0; l < 8; ++l) {
                    float a2 = Ds[(j0 + l) * LD + v];
                    #pragma unroll
                    for (int m = 0; m < 8; ++m)
                        if (m < l) a2 -= Asm[(j0 + l) * LA + j0 + m] * dv[m];
                    dv[l] = Bts[j0 + l] * a2;
                }
                #pragma unroll
                for (int l = 0; l < 8; ++l) Ds[(j0 + l) * LD + v] = dv[l];
            }
            __syncthreads();
            int rem = (7 - blk) * 8;
            for (int idx = tid; idx < rem * VHW; idx += 256) {
                int i = j0 + 8 + (idx >> 5), v = idx & 31;
                float a2 = Ds[i * LD + v];
                #pragma unroll
                for (int l = 0; l < 8; ++l)
                    a2 -= Asm[i * LA + j0 + l] * Ds[(j0 + l) * LD + v];
                Ds[i * LD + v] = a2;
            }
            __syncthreads();
        }

        // (7) OUT = trilG D + Q Whit + Q Wlot  [64x32] -> g_att
        {
            float acc[2][4];
            #pragma unroll
            for (int i = 0; i < 2; ++i)
                #pragma unroll
                for (int r = 0; r < 4; ++r) acc[i][r] = 0.f;
            gemm_block(Gsm, LA, true, false, Ds, LD, true, true,
                       acc, 2, 16 * wr, 16 * wc, 64, g, t4);
            gemm_block(Qc, LKQ, false, false, Whi, LKQ, false, false,
                       acc, 2, 16 * wr, 16 * wc, 128, g, t4);
            gemm_block(Qc, LKQ, false, false, Wlo, LKQ, false, false,
                       acc, 2, 16 * wr, 16 * wc, 128, g, t4);
            uint32_t* ao = reinterpret_cast<uint32_t*>(att);
            #pragma unroll
            for (int nt = 0; nt < 2; ++nt) {
                int r0 = 16 * wr + g, cc = 16 * wc + nt * 8 + 2 * t4;
                size_t base0 = (size_t)(c * CT + r0) * (BATCH * DM) + b * DM + h * DK + vh * VHW + cc;
                size_t base1 = base0 + (size_t)8 * (BATCH * DM);
                ao[base0]     = f2tf32(acc[nt][0]);
                ao[base0 + 1] = f2tf32(acc[nt][1]);
                ao[base1]     = f2tf32(acc[nt][2]);
                ao[base1 + 1] = f2tf32(acc[nt][3]);
            }
        }
        __syncthreads();

        // (6) W += Dt K  [32x128], k=64; hi/lo recombine
        {
            float acc[4][4];
            #pragma unroll
            for (int i = 0; i < 4; ++i)
                #pragma unroll
                for (int r = 0; r < 4; ++r) acc[i][r] = 0.f;
            int m0 = 16 * (w & 1), n0 = 32 * (w >> 1);
            gemm_block(Ds, LD, true, true, Kc, LKQ, false, true,
                       acc, 4, m0, n0, 64, g, t4);
            #pragma unroll
            for (int nt = 0; nt < 4; ++nt) {
                int r0 = m0 + g, cc = n0 + nt * 8 + 2 * t4;
                #pragma unroll
                for (int rr = 0; rr < 2; ++rr) {
                    int rv = r0 + rr * 8;
                    #pragma unroll
                    for (int e = 0; e < 2; ++e) {
                        int idx = rv * LKQ + cc + e;
                        float s2 = Whi[idx] + Wlo[idx] + acc[nt][rr * 2 + e];
                        float hi = rnd_tf32(s2);
                        Whi[idx] = hi;
                        Wlo[idx] = rnd_tf32(s2 - hi);
                    }
                }
            }
        }
        __syncthreads();
    }
}

// ---------------------------------------------------------------------------
// Host launcher
// ---------------------------------------------------------------------------
extern "C" void kernel_launch(void* const* d_in, const int* in_sizes, int n_in,
                              void* d_out, int out_size)
{
    const float* x  = (const float*)d_in[0];
    const float* Wq = (const float*)d_in[1];
    const float* Wk = (const float*)d_in[2];
    const float* Wv = (const float*)d_in[3];
    const float* Wg = (const float*)d_in[4];
    const float* Wo = (const float*)d_in[5];
    const float* bo = (const float*)d_in[6];
    float* out = (float*)d_out;

    float *xr, *wcat, *wo, *qkv, *qphi, *kphi, *bcv, *attb;
    cudaGetSymbolAddress((void**)&xr,    g_xr);
    cudaGetSymbolAddress((void**)&wcat,  g_wcat);
    cudaGetSymbolAddress((void**)&wo,    g_wo);
    cudaGetSymbolAddress((void**)&qkv,   g_qkv);
    cudaGetSymbolAddress((void**)&qphi,  g_qphi);
    cudaGetSymbolAddress((void**)&kphi,  g_kphi);
    cudaGetSymbolAddress((void**)&bcv,   g_bc);
    cudaGetSymbolAddress((void**)&attb,  g_att);

    cudaFuncSetAttribute(gemm_tf32, cudaFuncAttributeMaxDynamicSharedMemorySize,
                         GEMM_SMEM_BYTES);
    cudaFuncSetAttribute(chunk_kernel, cudaFuncAttributeMaxDynamicSharedMemorySize,
                         CH_SMEM_BYTES);

    // pre-round inputs to tf32
    round_f4<<<(ROWS * DM) / 1024, 256>>>(x, xr);
    concat_w<<<(DM * NG) / 256, 256>>>(Wq, Wk, Wv, Wg, wcat);
    round_f4<<<(DM * DM) / 1024, 256>>>(Wo, wo);

    // fused QKV + gate GEMM: [32768,512] x [512,1664]
    dim3 g1(NG / BN, ROWS / BM);
    gemm_tf32<<<g1, 256, GEMM_SMEM_BYTES>>>(xr, wcat, nullptr, qkv, ROWS, NG, DM);

    extract_beta<<<(ROWS * NHEAD) / 256, 256>>>(qkv, bcv);
    dpfp_kernel<<<ROWS, 256>>>(qkv + 512, kphi);
    dpfp_kernel<<<ROWS, 256>>>(qkv,       qphi);

    // chunked delta rule: 128 CTAs = 64 pairs x 2 v-halves
    chunk_kernel<<<128, 256, CH_SMEM_BYTES>>>(qphi, kphi, qkv, bcv, attb);

    dim3 g2(DM / BN, ROWS / BM);
    gemm_tf32<<<g2, 256, GEMM_SMEM_BYTES>>>(attb, wo, bo, out, ROWS, DM, DM);
}

// round 14
// speedup vs baseline: 1.0019x; 1.0019x over previous
#include <cuda_runtime.h>
#include <cstdint>
#include <cstddef>

#define SEQ   4096
#define BATCH 8
#define DM    512
#define NHEAD 8
#define DK    64
#define PHI   128
#define ROWS  (SEQ * BATCH)    // 32768 tokens
#define NG    1664             // fused QKV+gate GEMM width
#define PAD   4

typedef unsigned long long ull;

// ---------------------------------------------------------------------------
// Static device scratch
// ---------------------------------------------------------------------------
__device__ float g_xr  [(size_t)ROWS * DM];
__device__ float g_wcat[(size_t)DM * NG];
__device__ float g_wo  [(size_t)DM * DM];
__device__ float g_qkv [(size_t)(ROWS + PAD * BATCH) * NG];
__device__ float g_qphi[(size_t)(ROWS + PAD * BATCH) * NHEAD * PHI];
__device__ float g_kphi[(size_t)(ROWS + PAD * BATCH) * NHEAD * PHI];
__device__ float g_bc  [(size_t)(ROWS + PAD * BATCH) * NHEAD * 2];
__device__ float g_att [(size_t)ROWS * DM];

// ---------------------------------------------------------------------------
// helpers
// ---------------------------------------------------------------------------
__device__ __forceinline__ uint32_t f2tf32(float x) {
    uint32_t r;
    asm("cvt.rna.tf32.f32 %0, %1;" : "=r"(r) : "f"(x));
    return r;
}
__device__ __forceinline__ float rnd_tf32(float x) {
    return __uint_as_float(f2tf32(x));
}
__device__ __forceinline__ void mma_tf32(float c[4], const uint32_t a[4], const uint32_t b[2]) {
    asm volatile(
        "mma.sync.aligned.m16n8k8.row.col.f32.tf32.tf32.f32 "
        "{%0,%1,%2,%3}, {%4,%5,%6,%7}, {%8,%9}, {%0,%1,%2,%3};\n"
        : "+f"(c[0]), "+f"(c[1]), "+f"(c[2]), "+f"(c[3])
        : "r"(a[0]), "r"(a[1]), "r"(a[2]), "r"(a[3]), "r"(b[0]), "r"(b[1]));
}
__device__ __forceinline__ void cp_async16(uint32_t s, const void* g) {
    asm volatile("cp.async.cg.shared.global [%0], [%1], 16;\n" :: "r"(s), "l"(g));
}
__device__ __forceinline__ void cp_commit() {
    asm volatile("cp.async.commit_group;\n" ::: "memory");
}
__device__ __forceinline__ void cp_wait0() {
    asm volatile("cp.async.wait_group 0;\n" ::: "memory");
}
__device__ __forceinline__ uint32_t ldu(const float* p) {
    return *reinterpret_cast<const uint32_t*>(p);
}

// ---------------------------------------------------------------------------
// Elementwise pre-round passes
// ---------------------------------------------------------------------------
__global__ void __launch_bounds__(256)
round_f4(const float* __restrict__ in, float* __restrict__ out) {
    size_t i = ((size_t)blockIdx.x * 256 + threadIdx.x) * 4;
    float4 v = *reinterpret_cast<const float4*>(in + i);
    v.x = rnd_tf32(v.x); v.y = rnd_tf32(v.y); v.z = rnd_tf32(v.z); v.w = rnd_tf32(v.w);
    *reinterpret_cast<float4*>(out + i) = v;
}

__global__ void __launch_bounds__(256)
concat_w(const float* __restrict__ Wq, const float* __restrict__ Wk,
         const float* __restrict__ Wv, const float* __restrict__ Wg,
         float* __restrict__ wc) {
    int idx = blockIdx.x * 256 + threadIdx.x;
    int r = idx / NG, c = idx - r * NG;
    float v = 0.f;
    if      (c < 512)  v = Wq[r * 512 + c];
    else if (c < 1024) v = Wk[r * 512 + c - 512];
    else if (c < 1536) v = Wv[r * 512 + c - 1024];
    else if (c < 1544) v = Wg[r * 8 + c - 1536];
    wc[idx] = rnd_tf32(v);
}

// ---------------------------------------------------------------------------
// GEMM: C = A*B (+bias), tf32 tensor cores, 128x128x32, cp.async pipelined.
// ---------------------------------------------------------------------------
#define BM 128
#define BN 128
#define BK 32
#define AST 36
#define BST 136
#define STAGE_F (BM * AST + BK * BST)
#define GEMM_SMEM_BYTES (2 * STAGE_F * 4)

__global__ void __launch_bounds__(256, 2)
gemm_tf32(const float* __restrict__ A, const float* __restrict__ B,
          const float* __restrict__ bias, float* __restrict__ C,
          int M, int N, int K)
{
    extern __shared__ float smemf[];

    const int tid  = threadIdx.x;
    const int warp = tid >> 5;
    const int lane = tid & 31;
    const int wm   = warp >> 2;
    const int wn   = warp & 3;
    const int g    = lane >> 2;
    const int t4   = lane & 3;
    const int rowBase = blockIdx.y * BM;
    const int colBase = blockIdx.x * BN;

    const int ar = tid >> 3, ac = (tid & 7) << 2;
    const int br = tid >> 5, bc = (tid & 31) << 2;

    float acc[4][4][4];
    #pragma unroll
    for (int i = 0; i < 4; ++i)
        #pragma unroll
        for (int j = 0; j < 4; ++j)
            #pragma unroll
            for (int r = 0; r < 4; ++r) acc[i][j][r] = 0.f;

    auto load_tile = [&](int stage, int k0) {
        float* as = smemf + stage * STAGE_F;
        float* bs = as + BM * AST;
        const float* ag = A + (size_t)(rowBase + ar) * K + k0 + ac;
        uint32_t asa = (uint32_t)__cvta_generic_to_shared(as + ar * AST + ac);
        #pragma unroll
        for (int i = 0; i < 4; ++i)
            cp_async16(asa + i * 32 * AST * 4, ag + (size_t)i * 32 * K);
        const float* bg = B + (size_t)(k0 + br) * N + colBase + bc;
        uint32_t bsa = (uint32_t)__cvta_generic_to_shared(bs + br * BST + bc);
        #pragma unroll
        for (int i = 0; i < 4; ++i)
            cp_async16(bsa + i * 8 * BST * 4, bg + (size_t)i * 8 * N);
        cp_commit();
    };

    const int NK = K / BK;
    load_tile(0, 0);

    for (int it = 0; it < NK; ++it) {
        cp_wait0();
        __syncthreads();
        if (it + 1 < NK) load_tile((it + 1) & 1, (it + 1) * BK);

        const uint32_t* as = reinterpret_cast<const uint32_t*>(smemf + (it & 1) * STAGE_F);
        const uint32_t* bs = as + BM * AST;

        #pragma unroll
        for (int kk = 0; kk < BK; kk += 8) {
            uint32_t afr[4][4];
            uint32_t bfr[4][2];
            #pragma unroll
            for (int mt = 0; mt < 4; ++mt) {
                int r0 = wm * 64 + mt * 16;
                afr[mt][0] = as[(r0 + g)     * AST + kk + t4];
                afr[mt][1] = as[(r0 + 8 + g) * AST + kk + t4];
                afr[mt][2] = as[(r0 + g)     * AST + kk + 4 + t4];
                afr[mt][3] = as[(r0 + 8 + g) * AST + kk + 4 + t4];
            }
            #pragma unroll
            for (int nt = 0; nt < 4; ++nt) {
                int c0 = wn * 32 + nt * 8;
                bfr[nt][0] = bs[(kk + t4)     * BST + c0 + g];
                bfr[nt][1] = bs[(kk + 4 + t4) * BST + c0 + g];
            }
            #pragma unroll
            for (int mt = 0; mt < 4; ++mt)
                #pragma unroll
                for (int nt = 0; nt < 4; ++nt)
                    mma_tf32(acc[mt][nt], afr[mt], bfr[nt]);
        }
    }

    #pragma unroll
    for (int mt = 0; mt < 4; ++mt) {
        int r = rowBase + wm * 64 + mt * 16 + g;
        #pragma unroll
        for (int nt = 0; nt < 4; ++nt) {
            int c = colBase + wn * 32 + nt * 8 + 2 * t4;
            float b0 = 0.f, b1 = 0.f;
            if (bias) { b0 = bias[c]; b1 = bias[c + 1]; }
            C[(size_t)r * N + c]           = acc[mt][nt][0] + b0;
            C[(size_t)r * N + c + 1]       = acc[mt][nt][1] + b1;
            C[(size_t)(r + 8) * N + c]     = acc[mt][nt][2] + b0;
            C[(size_t)(r + 8) * N + c + 1] = acc[mt][nt][3] + b1;
        }
    }
}

// ---------------------------------------------------------------------------
// bc[t,h].x = sigmoid(qkv[t,1536+h])
// ---------------------------------------------------------------------------
__global__ void __launch_bounds__(256)
extract_beta(const float* __restrict__ qkv, float* __restrict__ bcv) {
    int idx = blockIdx.x * 256 + threadIdx.x;
    int t = idx >> 3, h = idx & 7;
    float a = qkv[(size_t)t * NG + 1536 + h];
    bcv[idx * 2] = 1.f / (1.f + expf(-a));
}

// ---------------------------------------------------------------------------
// DPFP. One warp per (token, head).
// ---------------------------------------------------------------------------
__global__ void __launch_bounds__(256)
dpfp_kernel(const float* __restrict__ raw, float* __restrict__ phi)
{
    const int t    = blockIdx.x;
    const int h    = threadIdx.x >> 5;
    const int lane = threadIdx.x & 31;

    const float4 xv = *reinterpret_cast<const float4*>(
        raw + (size_t)t * NG + h * DK + ((lane & 15) << 2));
    const float sgn = (lane < 16) ? 1.f : -1.f;
    float a0 = fmaxf(sgn * xv.x, 0.f);
    float a1 = fmaxf(sgn * xv.y, 0.f);
    float a2 = fmaxf(sgn * xv.z, 0.f);
    float a3 = fmaxf(sgn * xv.w, 0.f);

    float nbr = __shfl_sync(0xffffffffu, a3, (lane + 31) & 31);
    float y0 = a0 * nbr;
    float y1 = a1 * a0;
    float y2 = a2 * a1;
    float y3 = a3 * a2;

    float s = (y0 + y1) + (y2 + y3);
    #pragma unroll
    for (int off = 16; off > 0; off >>= 1)
        s += __shfl_xor_sync(0xffffffffu, s, off);
    float r = 1.f / (s + 1e-6f);

    float4 o = make_float4(y0 * r, y1 * r, y2 * r, y3 * r);
    *reinterpret_cast<float4*>(phi + ((size_t)t * NHEAD + h) * PHI + (lane << 2)) = o;
}

// ---------------------------------------------------------------------------
// Chunked delta rule. 128 CTAs: (pair = b*8+h, v-half). 64 chunks of 64
// tokens. Per chunk (tf32 MMA, W carried as hi+lo tf32 pair ~ fp32):
//   A = K Kt; G = tril(Q Kt); rhs = V - K Wt; forward-substitute D;
//   OUT = trilG D + Q Wt; W += Dt K.
// ---------------------------------------------------------------------------
#define NCH   64
#define CT    64
#define VHW   32
#define LKQ   132
#define LA    68
#define LD    36
#define OKQ_ST (CT * LKQ)                 // 8448 floats per K/Q stage
#define OFF_K   0
#define OFF_Q   (2 * OKQ_ST)              // 16896
#define OFF_WHI (4 * OKQ_ST)              // 33792
#define OFF_WLO (OFF_WHI + VHW * LKQ)     // 38016
#define OFF_A   (OFF_WLO + VHW * LKQ)     // 42240
#define OFF_G   (OFF_A + CT * LA)         // 46592
#define OFF_V   (OFF_G + CT * LA)         // 50944
#define OFF_D   (OFF_V + CT * LD)         // 53248
#define OFF_B   (OFF_D + CT * LD)         // 55552
#define CH_SMEM_F (OFF_B + 64)            // 55616
#define CH_SMEM_BYTES (CH_SMEM_F * 4)     // 222464

// one warp-level tiled GEMM pass accumulating into acc[NT][4]
__device__ __forceinline__ void gemm_block(
    const float* As, int lda, bool cvtA, bool trA,
    const float* Bsm, int ldb, bool cvtB, bool trB,
    float acc[][4], int NT, int m0, int n0, int K, int g, int t4)
{
    for (int kk = 0; kk < K; kk += 8) {
        uint32_t a[4];
        if (!trA) {
            const float* p0 = As + (m0 + g) * lda + kk + t4;
            const float* p1 = As + (m0 + 8 + g) * lda + kk + t4;
            a[0] = ldu(p0); a[1] = ldu(p1); a[2] = ldu(p0 + 4); a[3] = ldu(p1 + 4);
        } else {
            const float* p0 = As + (kk + t4) * lda + m0 + g;
            const float* p1 = As + (kk + 4 + t4) * lda + m0 + g;
            a[0] = ldu(p0); a[1] = ldu(p0 + 8); a[2] = ldu(p1); a[3] = ldu(p1 + 8);
        }
        if (cvtA) {
            #pragma unroll
            for (int i = 0; i < 4; ++i) a[i] = f2tf32(__uint_as_float(a[i]));
        }
        for (int nt = 0; nt < NT; ++nt) {
            uint32_t bfr[2];
            int nb = n0 + nt * 8 + g;
            if (!trB) {
                bfr[0] = ldu(Bsm + nb * ldb + kk + t4);
                bfr[1] = ldu(Bsm + nb * ldb + kk + 4 + t4);
            } else {
                bfr[0] = ldu(Bsm + (kk + t4) * ldb + nb);
                bfr[1] = ldu(Bsm + (kk + 4 + t4) * ldb + nb);
            }
            if (cvtB) {
                bfr[0] = f2tf32(__uint_as_float(bfr[0]));
                bfr[1] = f2tf32(__uint_as_float(bfr[1]));
            }
            mma_tf32(acc[nt], a, bfr);
        }
    }
}

__global__ void __launch_bounds__(256, 1)
chunk_kernel(const float* __restrict__ qphi, const float* __restrict__ kphi,
             const float* __restrict__ qkv, const float* __restrict__ bcv,
             float* __restrict__ att)
{
    extern __shared__ float sm[];
    const int tid  = threadIdx.x;
    const int w    = tid >> 5;
    const int lane = tid & 31;
    const int g    = lane >> 2;
    const int t4   = lane & 3;
    const int pair = blockIdx.x >> 1;
    const int vh   = blockIdx.x & 1;
    const int b    = pair >> 3;
    const int h    = pair & 7;

    float* Ks  = sm + OFF_K;
    float* Qs  = sm + OFF_Q;
    float* Whi = sm + OFF_WHI;
    float* Wlo = sm + OFF_WLO;
    float* Asm = sm + OFF_A;
    float* Gsm = sm + OFF_G;
    float* Vs  = sm + OFF_V;
    float* Ds  = sm + OFF_D;
    float* Bts = sm + OFF_B;

    // zero W
    for (int idx = tid; idx < VHW * LKQ; idx += 256) { Whi[idx] = 0.f; Wlo[idx] = 0.f; }

    const int wr = w & 3, wc = w >> 2;

    // issue cp.async for chunk c's K and Q into stage c&1
    auto issueKQ = [&](int c) {
        int st = (c & 1) * OKQ_ST;
        for (int idx = tid; idx < 2048; idx += 256) {
            int i = idx >> 5, sg = idx & 31;
            size_t s_time = (size_t)c * CT + i;
            const float* ksrc = kphi + s_time * 8192 + pair * PHI + sg * 4;
            const float* qsrc = qphi + s_time * 8192 + pair * PHI + sg * 4;
            cp_async16((uint32_t)__cvta_generic_to_shared(Ks + st + i * LKQ + sg * 4), ksrc);
            cp_async16((uint32_t)__cvta_generic_to_shared(Qs + st + i * LKQ + sg * 4), qsrc);
        }
        cp_commit();
    };

    issueKQ(0);

    for (int c = 0; c < NCH; ++c) {
        const int st = (c & 1) * OKQ_ST;
        const float* Kc = Ks + st;
        const float* Qc = Qs + st;

        // V + beta loads for this chunk
        for (int idx = tid; idx < 512; idx += 256) {
            int i = idx >> 3, sg = idx & 7;
            const float4 v4 = *reinterpret_cast<const float4*>(
                qkv + (size_t)((c * CT + i) * BATCH + b) * NG + 1024 + h * DK + vh * VHW + sg * 4);
            Vs[i * LD + sg * 4 + 0] = v4.x;
            Vs[i * LD + sg * 4 + 1] = v4.y;
            Vs[i * LD + sg * 4 + 2] = v4.z;
            Vs[i * LD + sg * 4 + 3] = v4.w;
        }
        if (tid < 64)
            Bts[tid] = bcv[((size_t)(c * CT + tid) * 64 + pair) * 2];

        cp_wait0();
        __syncthreads();

        // convert K/Q stage to tf32 in place
        for (int idx = tid; idx < 8192; idx += 256) {
            int i = idx >> 7, col = idx & 127;
            float* kp = const_cast<float*>(Kc) + i * LKQ + col;
            float* qp = const_cast<float*>(Qc) + i * LKQ + col;
            *kp = rnd_tf32(*kp);
            *qp = rnd_tf32(*qp);
        }
        __syncthreads();

        if (c + 1 < NCH) issueKQ(c + 1);

        // (1) A = K Kt  [64x64], k=128   (store fp32)
        {
            float acc[4][4];
            #pragma unroll
            for (int i = 0; i < 4; ++i)
                #pragma unroll
                for (int r = 0; r < 4; ++r) acc[i][r] = 0.f;
            gemm_block(Kc, LKQ, false, false, Kc, LKQ, false, false,
                       acc, 4, 16 * wr, 32 * wc, 128, g, t4);
            #pragma unroll
            for (int nt = 0; nt < 4; ++nt) {
                int r0 = 16 * wr + g, cc = 32 * wc + nt * 8 + 2 * t4;
                Asm[r0 * LA + cc]           = acc[nt][0];
                Asm[r0 * LA + cc + 1]       = acc[nt][1];
                Asm[(r0 + 8) * LA + cc]     = acc[nt][2];
                Asm[(r0 + 8) * LA + cc + 1] = acc[nt][3];
            }
        }
        // (2) G = tril(Q Kt) incl diag  (store fp32, masked)
        {
            float acc[4][4];
            #pragma unroll
            for (int i = 0; i < 4; ++i)
                #pragma unroll
                for (int r = 0; r < 4; ++r) acc[i][r] = 0.f;
            gemm_block(Qc, LKQ, false, false, Kc, LKQ, false, false,
                       acc, 4, 16 * wr, 32 * wc, 128, g, t4);
            #pragma unroll
            for (int nt = 0; nt < 4; ++nt) {
                int r0 = 16 * wr + g, cc = 32 * wc + nt * 8 + 2 * t4;
                Gsm[r0 * LA + cc]           = (cc     <= r0)     ? acc[nt][0] : 0.f;
                Gsm[r0 * LA + cc + 1]       = (cc + 1 <= r0)     ? acc[nt][1] : 0.f;
                Gsm[(r0 + 8) * LA + cc]     = (cc     <= r0 + 8) ? acc[nt][2] : 0.f;
                Gsm[(r0 + 8) * LA + cc + 1] = (cc + 1 <= r0 + 8) ? acc[nt][3] : 0.f;
            }
        }
        // (3) rhs = V - K Wt  [64x32], k=128 twice (hi, lo)
        {
            float acc[2][4];
            #pragma unroll
            for (int i = 0; i < 2; ++i)
                #pragma unroll
                for (int r = 0; r < 4; ++r) acc[i][r] = 0.f;
            gemm_block(Kc, LKQ, false, false, Whi, LKQ, false, false,
                       acc, 2, 16 * wr, 16 * wc, 128, g, t4);
            gemm_block(Kc, LKQ, false, false, Wlo, LKQ, false, false,
                       acc, 2, 16 * wr, 16 * wc, 128, g, t4);
            #pragma unroll
            for (int nt = 0; nt < 2; ++nt) {
                int r0 = 16 * wr + g, cc = 16 * wc + nt * 8 + 2 * t4;
                Ds[r0 * LD + cc]           = Vs[r0 * LD + cc]           - acc[nt][0];
                Ds[r0 * LD + cc + 1]       = Vs[r0 * LD + cc + 1]       - acc[nt][1];
                Ds[(r0 + 8) * LD + cc]     = Vs[(r0 + 8) * LD + cc]     - acc[nt][2];
                Ds[(r0 + 8) * LD + cc + 1] = Vs[(r0 + 8) * LD + cc + 1] - acc[nt][3];
            }
        }
        __syncthreads();

        // forward substitution: d_i = beta_i (rhs_i - sum_{j<i} A[i,j] d_j)
        // blocked by 8 tokens: serial in-block solve (32 threads), rank-8 update
        for (int blk = 0; blk < 8; ++blk) {
            int j0 = blk * 8;
            if (tid < VHW) {
                int v = tid;
                float dv[8];
                #pragma unroll
                for (int l = 0; l < 8; ++l) {
                    float a2 = Ds[(j0 + l) * LD + v];
                    #pragma unroll
                    for (int m = 0; m < 8; ++m)
                        if (m < l) a2 -= Asm[(j0 + l) * LA + j0 + m] * dv[m];
                    dv[l] = Bts[j0 + l] * a2;
                }
                #pragma unroll
                for (int l = 0; l < 8; ++l) Ds[(j0 + l) * LD + v] = dv[l];
            }
            __syncthreads();
            int rem = (7 - blk) * 8;
            for (int idx = tid; idx < rem * VHW; idx += 256) {
                int i = j0 + 8 + (idx >> 5), v = idx & 31;
                float a2 = Ds[i * LD + v];
                #pragma unroll
                for (int l = 0; l < 8; ++l)
                    a2 -= Asm[i * LA + j0 + l] * Ds[(j0 + l) * LD + v];
                Ds[i * LD + v] = a2;
            }
            __syncthreads();
        }

        // (7) OUT = trilG D + Q Whit + Q Wlot  [64x32] -> g_att
        {
            float acc[2][4];
            #pragma unroll
            for (int i = 0; i < 2; ++i)
                #pragma unroll
                for (int r = 0; r < 4; ++r) acc[i][r] = 0.f;
            gemm_block(Gsm, LA, true, false, Ds, LD, true, true,
                       acc, 2, 16 * wr, 16 * wc, 64, g, t4);
            gemm_block(Qc, LKQ, false, false, Whi, LKQ, false, false,
                       acc, 2, 16 * wr, 16 * wc, 128, g, t4);
            gemm_block(Qc, LKQ, false, false, Wlo, LKQ, false, false,
                       acc, 2, 16 * wr, 16 * wc, 128, g, t4);
            uint32_t* ao = reinterpret_cast<uint32_t*>(att);
            #pragma unroll
            for (int nt = 0; nt < 2; ++nt) {
                int r0 = 16 * wr + g, cc = 16 * wc + nt * 8 + 2 * t4;
                size_t base0 = (size_t)(c * CT + r0) * (BATCH * DM) + b * DM + h * DK + vh * VHW + cc;
                size_t base1 = base0 + (size_t)8 * (BATCH * DM);
                ao[base0]     = f2tf32(acc[nt][0]);
                ao[base0 + 1] = f2tf32(acc[nt][1]);
                ao[base1]     = f2tf32(acc[nt][2]);
                ao[base1 + 1] = f2tf32(acc[nt][3]);
            }
        }
        __syncthreads();

        // (6) W += Dt K  [32x128], k=64; hi/lo recombine
        {
            float acc[4][4];
            #pragma unroll
            for (int i = 0; i < 4; ++i)
                #pragma unroll
                for (int r = 0; r < 4; ++r) acc[i][r] = 0.f;
            int m0 = 16 * (w & 1), n0 = 32 * (w >> 1);
            gemm_block(Ds, LD, true, true, Kc, LKQ, false, true,
                       acc, 4, m0, n0, 64, g, t4);
            #pragma unroll
            for (int nt = 0; nt < 4; ++nt) {
                int r0 = m0 + g, cc = n0 + nt * 8 + 2 * t4;
                #pragma unroll
                for (int rr = 0; rr < 2; ++rr) {
                    int rv = r0 + rr * 8;
                    #pragma unroll
                    for (int e = 0; e < 2; ++e) {
                        int idx = rv * LKQ + cc + e;
                        float s2 = Whi[idx] + Wlo[idx] + acc[nt][rr * 2 + e];
                        float hi = rnd_tf32(s2);
                        Whi[idx] = hi;
                        Wlo[idx] = rnd_tf32(s2 - hi);
                    }
                }
            }
        }
        __syncthreads();
    }
}

// ---------------------------------------------------------------------------
// Host launcher
// ---------------------------------------------------------------------------
extern "C" void kernel_launch(void* const* d_in, const int* in_sizes, int n_in,
                              void* d_out, int out_size)
{
    const float* x  = (const float*)d_in[0];
    const float* Wq = (const float*)d_in[1];
    const float* Wk = (const float*)d_in[2];
    const float* Wv = (const float*)d_in[3];
    const float* Wg = (const float*)d_in[4];
    const float* Wo = (const float*)d_in[5];
    const float* bo = (const float*)d_in[6];
    float* out = (float*)d_out;

    float *xr, *wcat, *wo, *qkv, *qphi, *kphi, *bcv, *attb;
    cudaGetSymbolAddress((void**)&xr,    g_xr);
    cudaGetSymbolAddress((void**)&wcat,  g_wcat);
    cudaGetSymbolAddress((void**)&wo,    g_wo);
    cudaGetSymbolAddress((void**)&qkv,   g_qkv);
    cudaGetSymbolAddress((void**)&qphi,  g_qphi);
    cudaGetSymbolAddress((void**)&kphi,  g_kphi);
    cudaGetSymbolAddress((void**)&bcv,   g_bc);
    cudaGetSymbolAddress((void**)&attb,  g_att);

    cudaFuncSetAttribute(gemm_tf32, cudaFuncAttributeMaxDynamicSharedMemorySize,
                         GEMM_SMEM_BYTES);
    cudaFuncSetAttribute(chunk_kernel, cudaFuncAttributeMaxDynamicSharedMemorySize,
                         CH_SMEM_BYTES);

    // pre-round inputs to tf32
    round_f4<<<(ROWS * DM) / 1024, 256>>>(x, xr);
    concat_w<<<(DM * NG) / 256, 256>>>(Wq, Wk, Wv, Wg, wcat);
    round_f4<<<(DM * DM) / 1024, 256>>>(Wo, wo);

    // fused QKV + gate GEMM: [32768,512] x [512,1664]
    dim3 g1(NG / BN, ROWS / BM);
    gemm_tf32<<<g1, 256, GEMM_SMEM_BYTES>>>(xr, wcat, nullptr, qkv, ROWS, NG, DM);

    extract_beta<<<(ROWS * NHEAD) / 256, 256>>>(qkv, bcv);
    dpfp_kernel<<<ROWS, 256>>>(qkv + 512, kphi);
    dpfp_kernel<<<ROWS, 256>>>(qkv,       qphi);

    // chunked delta rule: 128 CTAs = 64 pairs x 2 v-halves
    chunk_kernel<<<128, 256, CH_SMEM_BYTES>>>(qphi, kphi, qkv, bcv, attb);

    dim3 g2(DM / BN, ROWS / BM);
    gemm_tf32<<<g2, 256, GEMM_SMEM_BYTES>>>(attb, wo, bo, out, ROWS, DM, DM);
}